// round 15
// baseline (speedup 1.0000x reference)
#include <cuda_runtime.h>
#include <cuda_fp16.h>
#include <math.h>
#include <stdint.h>

#define NTOK 1024
#define DMODEL 512
#define BATCH 8
#define DEPTH 4
#define ROWS (BATCH*NTOK)   // 8192

// ---------------- scratch (static device globals; no runtime allocation) ----
__device__ float g_t  [ROWS*DMODEL];
__device__ __half g_qkv[ROWS*3*DMODEL];
__device__ __half g_hh [ROWS*DMODEL];
__device__ __half g_oh [ROWS*DMODEL];
__device__ __half g_f1 [ROWS*2*DMODEL];
__device__ __half g_wqkv[DEPTH*3*DMODEL*DMODEL];
__device__ __half g_wout[DEPTH*DMODEL*DMODEL];
__device__ __half g_w1[2*DMODEL*DMODEL];
__device__ __half g_w2[2*DMODEL*DMODEL];

// ---------------- helpers ----------------------------------------------------
__device__ __forceinline__ uint32_t pack2h(float a, float b) {
    __half2 hp = __halves2half2(__float2half_rn(a), __float2half_rn(b));
    return *(uint32_t*)&hp;
}
__device__ __forceinline__ void ldsm4(uint32_t& r0, uint32_t& r1, uint32_t& r2, uint32_t& r3,
                                      uint32_t addr) {
    asm volatile("ldmatrix.sync.aligned.m8n8.x4.shared.b16 {%0,%1,%2,%3},[%4];"
                 : "=r"(r0), "=r"(r1), "=r"(r2), "=r"(r3) : "r"(addr));
}
__device__ __forceinline__ void ldsm4t(uint32_t& r0, uint32_t& r1, uint32_t& r2, uint32_t& r3,
                                       uint32_t addr) {
    asm volatile("ldmatrix.sync.aligned.m8n8.x4.trans.shared.b16 {%0,%1,%2,%3},[%4];"
                 : "=r"(r0), "=r"(r1), "=r"(r2), "=r"(r3) : "r"(addr));
}
__device__ __forceinline__ void mma_f16(float* c, const uint32_t* a, const uint32_t* b) {
    asm volatile(
        "mma.sync.aligned.m16n8k16.row.col.f32.f16.f16.f32 "
        "{%0,%1,%2,%3},{%4,%5,%6,%7},{%8,%9},{%0,%1,%2,%3};"
        : "+f"(c[0]), "+f"(c[1]), "+f"(c[2]), "+f"(c[3])
        : "r"(a[0]), "r"(a[1]), "r"(a[2]), "r"(a[3]), "r"(b[0]), "r"(b[1]));
}
__device__ __forceinline__ void cpasync16(uint32_t saddr, const void* g) {
    asm volatile("cp.async.cg.shared.global [%0],[%1],16;" :: "r"(saddr), "l"(g));
}
__device__ __forceinline__ float gelu_exact(float v) {
    return 0.5f * v * (1.0f + erff(v * 0.7071067811865476f));
}

// ---------------- fp16 convert of ALL weight tensors (one launch) -----------
__global__ void split_allh(const float* __restrict__ w0, __half* __restrict__ h0, int n0,
                           const float* __restrict__ w1, __half* __restrict__ h1, int n1,
                           const float* __restrict__ w2, __half* __restrict__ h2, int n2,
                           const float* __restrict__ w3, __half* __restrict__ h3, int n3) {
    int i = blockIdx.x * 256 + threadIdx.x;
    const float* w; __half* h;
    if (i < n0) { w = w0 + i; h = h0 + i; }
    else if (i < n0 + n1) { i -= n0; w = w1 + i; h = h1 + i; }
    else if (i < n0 + n1 + n2) { i -= n0 + n1; w = w2 + i; h = h2 + i; }
    else if (i < n0 + n1 + n2 + n3) { i -= n0 + n1 + n2; w = w3 + i; h = h3 + i; }
    else return;
    *h = __float2half_rn(*w);
}

// ---------------- embed: transpose [b,c,n] -> [b,n,c] + sinusoid PE ---------
__global__ void embed_kernel(const float* __restrict__ x, float* __restrict__ t) {
    __shared__ float tile[32][33];
    int n0 = blockIdx.x * 32, c0 = blockIdx.y * 32, b = blockIdx.z;
    int tx = threadIdx.x, ty = threadIdx.y;
#pragma unroll
    for (int i = 0; i < 4; i++) {
        int c = c0 + ty + i * 8;
        tile[ty + i * 8][tx] = x[((size_t)b * DMODEL + c) * NTOK + n0 + tx];
    }
    __syncthreads();
#pragma unroll
    for (int i = 0; i < 4; i++) {
        int n = n0 + ty + i * 8;
        int c = c0 + tx;
        float e = (float)(c & ~1) * (1.0f / DMODEL);
        float ang = (float)n * expf(-9.210340371976184f * e);
        float pe = (c & 1) ? cosf(ang) : sinf(ang);
        t[((size_t)b * NTOK + n) * DMODEL + c] = tile[tx][ty + i * 8] + pe;
    }
}

// ---------------- fused final LN + unembed transpose ------------------------
#define FLN_ST 513
__global__ void __launch_bounds__(256) ln_unembed_kernel(
    const float* __restrict__ t, const float* __restrict__ lw,
    const float* __restrict__ lb, float* __restrict__ out) {
    extern __shared__ float fsm[];
    const int tid = threadIdx.x, lane = tid & 31, w = tid >> 5;
    const int n0 = blockIdx.x * 32, b = blockIdx.y;

    const float4* wr = (const float4*)lw;
    const float4* br = (const float4*)lb;
#pragma unroll
    for (int rr = 0; rr < 4; rr++) {
        int rloc = w * 4 + rr;
        const float4* xr = (const float4*)(t + (size_t)(b * NTOK + n0 + rloc) * DMODEL);
        float4 v[4];
        float s = 0.0f;
#pragma unroll
        for (int u = 0; u < 4; u++) {
            v[u] = xr[u * 32 + lane];
            s += v[u].x + v[u].y + v[u].z + v[u].w;
        }
#pragma unroll
        for (int o = 16; o > 0; o >>= 1) s += __shfl_xor_sync(0xffffffffu, s, o);
        float mu = s * (1.0f / DMODEL);
        float q = 0.0f;
#pragma unroll
        for (int u = 0; u < 4; u++) {
            v[u].x -= mu; v[u].y -= mu; v[u].z -= mu; v[u].w -= mu;
            q += v[u].x * v[u].x + v[u].y * v[u].y + v[u].z * v[u].z + v[u].w * v[u].w;
        }
#pragma unroll
        for (int o = 16; o > 0; o >>= 1) q += __shfl_xor_sync(0xffffffffu, q, o);
        float rstd = rsqrtf(q * (1.0f / DMODEL) + 1e-5f);
        float* dst = fsm + rloc * FLN_ST;
#pragma unroll
        for (int u = 0; u < 4; u++) {
            float4 W = wr[u * 32 + lane], B = br[u * 32 + lane];
            int c = (u * 32 + lane) * 4;
            dst[c + 0] = v[u].x * rstd * W.x + B.x;
            dst[c + 1] = v[u].y * rstd * W.y + B.y;
            dst[c + 2] = v[u].z * rstd * W.z + B.z;
            dst[c + 3] = v[u].w * rstd * W.w + B.w;
        }
    }
    __syncthreads();

    const int nl = lane;
#pragma unroll 8
    for (int cb = 0; cb < DMODEL; cb += 8) {
        int c = cb + w;
        out[((size_t)b * DMODEL + c) * NTOK + n0 + nl] = fsm[nl * FLN_ST + c];
    }
}

// ---------------- layernorm -> fp16 plane (per-layer) -----------------------
__global__ void ln_kernel(const float* __restrict__ x, const float* __restrict__ w,
                          const float* __restrict__ bias, __half* __restrict__ yh) {
    int gw = (blockIdx.x * blockDim.x + threadIdx.x) >> 5;
    int lane = threadIdx.x & 31;
    if (gw >= ROWS) return;
    const float4* xr = (const float4*)(x + (size_t)gw * DMODEL);
    float4 v[4];
    float s = 0.0f;
#pragma unroll
    for (int u = 0; u < 4; u++) {
        v[u] = xr[u * 32 + lane];
        s += v[u].x + v[u].y + v[u].z + v[u].w;
    }
#pragma unroll
    for (int o = 16; o > 0; o >>= 1) s += __shfl_xor_sync(0xffffffffu, s, o);
    float mu = s * (1.0f / DMODEL);
    float q = 0.0f;
#pragma unroll
    for (int u = 0; u < 4; u++) {
        v[u].x -= mu; v[u].y -= mu; v[u].z -= mu; v[u].w -= mu;
        q += v[u].x * v[u].x + v[u].y * v[u].y + v[u].z * v[u].z + v[u].w * v[u].w;
    }
#pragma unroll
    for (int o = 16; o > 0; o >>= 1) q += __shfl_xor_sync(0xffffffffu, q, o);
    float rstd = rsqrtf(q * (1.0f / DMODEL) + 1e-5f);
    const float4* wr = (const float4*)w;
    const float4* br = (const float4*)bias;
#pragma unroll
    for (int u = 0; u < 4; u++) {
        float4 W = wr[u * 32 + lane], B = br[u * 32 + lane];
        float o0 = v[u].x * rstd * W.x + B.x;
        float o1 = v[u].y * rstd * W.y + B.y;
        float o2 = v[u].z * rstd * W.z + B.z;
        float o3 = v[u].w * rstd * W.w + B.w;
        size_t off = (size_t)gw * DMODEL + (u * 32 + lane) * 4;
        *(uint32_t*)(yh + off)     = pack2h(o0, o1);
        *(uint32_t*)(yh + off + 2) = pack2h(o2, o3);
    }
}

// ---------------- tensor-core GEMM (fp16): C = A * W^T ----------------------
// Block tile 128x256, 8 warps in 2x4 grid, warp tile 64x64. 2-stage cp.async.
#define BK 64
#define KST 72
#define PLANE_A (128*KST)            // 9216 halves
#define PLANE_B (256*KST)            // 18432 halves
#define STAGE (PLANE_A+PLANE_B)      // 27648 halves per stage
#define GEMM_SMEM (2*STAGE*2)        // 110592 bytes

// MODE 1: fp32 = acc+bias+resid. MODE 2: fp16 = gelu(acc+bias). MODE 3: fp16 = acc.
template <int MODE>
__global__ void __launch_bounds__(256) gemm_tc(
    const __half* __restrict__ Ah, const __half* __restrict__ Bh,
    const float* __restrict__ bias, const float* __restrict__ resid,
    float* __restrict__ C, __half* __restrict__ Ch,
    int N, int K) {
    extern __shared__ __half smbuf[];
    const int tid = threadIdx.x;
    const int lane = tid & 31, w = tid >> 5;
    const int wr = w >> 2, wc = w & 3;               // 2 x 4 warp grid
    const int m0 = blockIdx.y * 128, n0 = blockIdx.x * 256;
    const uint32_t smbase = (uint32_t)__cvta_generic_to_shared(smbuf);

    auto load_stage = [&](int it, int buf) {
        const int k0 = it * BK;
#pragma unroll
        for (int i = 0; i < 12; i++) {
            int c = tid + 256 * i;          // 0..3071
            uint32_t dst;
            const __half* src;
            if (c < 1024) {                 // A: 128 rows x 8 chunks
                int r = c >> 3, cc = (c & 7) * 8;
                src = Ah + (size_t)(m0 + r) * K + k0 + cc;
                dst = (uint32_t)(buf * STAGE + r * KST + cc);
            } else {                        // B: 256 rows x 8 chunks
                int cb = c - 1024;
                int r = cb >> 3, cc = (cb & 7) * 8;
                src = Bh + (size_t)(n0 + r) * K + k0 + cc;
                dst = (uint32_t)(buf * STAGE + PLANE_A + r * KST + cc);
            }
            cpasync16(smbase + dst * 2, src);
        }
    };

    float acc[4][8][4] = {};

    const int arow = wr * 64 + (lane & 15);
    const int acol = (lane >> 4) * 8;
    const int bn   = wc * 64 + ((lane >> 4) << 3) + (lane & 7);
    const int bk   = ((lane >> 3) & 1) << 3;

    const int niter = K / BK;
    load_stage(0, 0);
    asm volatile("cp.async.commit_group;");
    for (int it = 0; it < niter; ++it) {
        if (it + 1 < niter) {
            load_stage(it + 1, (it + 1) & 1);
            asm volatile("cp.async.commit_group;");
            asm volatile("cp.async.wait_group 1;");
        } else {
            asm volatile("cp.async.wait_group 0;");
        }
        __syncthreads();
        const uint32_t base = smbase + (uint32_t)(it & 1) * STAGE * 2;
#pragma unroll
        for (int kk = 0; kk < BK; kk += 16) {
            uint32_t af[4][4];
#pragma unroll
            for (int mt = 0; mt < 4; ++mt) {
                uint32_t ai = base + (uint32_t)((arow + mt * 16) * KST + kk + acol) * 2;
                ldsm4(af[mt][0], af[mt][1], af[mt][2], af[mt][3], ai);
            }
#pragma unroll
            for (int g = 0; g < 4; ++g) {
                uint32_t bf[4];
                uint32_t bi = base + PLANE_A * 2 +
                              (uint32_t)((bn + g * 16) * KST + kk + bk) * 2;
                ldsm4(bf[0], bf[1], bf[2], bf[3], bi);
#pragma unroll
                for (int half = 0; half < 2; ++half) {
                    int nt = 2 * g + half;
#pragma unroll
                    for (int mt = 0; mt < 4; ++mt)
                        mma_f16(acc[mt][nt], af[mt], bf + 2 * half);
                }
            }
        }
        __syncthreads();
    }

    const int erow = m0 + wr * 64 + (lane >> 2);
    const int ecol = n0 + wc * 64 + (lane & 3) * 2;
#pragma unroll
    for (int mt = 0; mt < 4; ++mt)
#pragma unroll
        for (int nt = 0; nt < 8; ++nt) {
            int c = ecol + nt * 8;
#pragma unroll
            for (int half = 0; half < 2; ++half) {
                int rr = erow + mt * 16 + half * 8;
                float v0 = acc[mt][nt][half * 2 + 0];
                float v1 = acc[mt][nt][half * 2 + 1];
                size_t off = (size_t)rr * N + c;
                if (MODE == 1) {
                    float2 rv = *(const float2*)(resid + off);
                    v0 += bias[c] + rv.x;
                    v1 += bias[c + 1] + rv.y;
                    *(float2*)(C + off) = make_float2(v0, v1);
                } else if (MODE == 2) {
                    v0 = gelu_exact(v0 + bias[c]);
                    v1 = gelu_exact(v1 + bias[c + 1]);
                    *(uint32_t*)(Ch + off) = pack2h(v0, v1);
                } else {
                    *(uint32_t*)(Ch + off) = pack2h(v0, v1);
                }
            }
        }
}

// ---------------- tensor-core flash attention (fp16, cp.async) --------------
#define AST 72
#define Q_ELE (128*AST)
#define KV_PLANE (64*AST)
#define STG_ELE (2*KV_PLANE)
#define ATT_SMEM ((Q_ELE + 2*STG_ELE)*2)   // 55296 bytes

__global__ void __launch_bounds__(256, 2) attn_tc(
    const __half* __restrict__ qkv, __half* __restrict__ oh) {
    extern __shared__ __half sb[];
    const uint32_t smb = (uint32_t)__cvta_generic_to_shared(sb);
    const int tid = threadIdx.x, lane = tid & 31, wid = tid >> 5;
    const int q0 = blockIdx.x * 128;
    const int b = blockIdx.y >> 3, h = blockIdx.y & 7;

    const __half* hbase = qkv + (size_t)(b * NTOK) * 1536 + h * 64;

#pragma unroll
    for (int i = 0; i < 4; i++) {
        int c = tid + 256 * i;
        int row = c >> 3, col = (c & 7) * 8;
        cpasync16(smb + (uint32_t)(row * AST + col) * 2,
                  hbase + (size_t)(q0 + row) * 1536 + col);
    }

    auto load_kv = [&](int kt, int buf) {
#pragma unroll
        for (int i = 0; i < 4; i++) {
            int c = tid + 256 * i;
            int plane = c >> 9, rem = c & 511;
            int row = rem >> 3, col = (rem & 7) * 8;
            const __half* src = hbase + (plane ? 1024 : 512) +
                                (size_t)(kt * 64 + row) * 1536 + col;
            uint32_t dst = (uint32_t)(Q_ELE + buf * STG_ELE + plane * KV_PLANE +
                                      row * AST + col) * 2;
            cpasync16(smb + dst, src);
        }
    };

    float oacc[8][4] = {};
    float m0s = -1e30f, m1s = -1e30f, l0s = 0.0f, l1s = 0.0f;
    const float sc = 0.18033688011112042f;

    load_kv(0, 0);
    asm volatile("cp.async.commit_group;");

    for (int kt = 0; kt < 16; kt++) {
        if (kt + 1 < 16) {
            load_kv(kt + 1, (kt + 1) & 1);
            asm volatile("cp.async.commit_group;");
            asm volatile("cp.async.wait_group 1;");
        } else {
            asm volatile("cp.async.wait_group 0;");
        }
        __syncthreads();
        const uint32_t base = (uint32_t)(Q_ELE + (kt & 1) * STG_ELE) * 2;

        float s[8][4] = {};
#pragma unroll
        for (int k8 = 0; k8 < 4; k8++) {
            uint32_t qf[4];
            uint32_t qa = smb + (uint32_t)((wid * 16 + (lane & 15)) * AST + k8 * 16 +
                                           ((lane >> 4) << 3)) * 2;
            ldsm4(qf[0], qf[1], qf[2], qf[3], qa);
#pragma unroll
            for (int g = 0; g < 4; g++) {
                int br = g * 16 + ((lane >> 4) << 3) + (lane & 7);
                int bc = k8 * 16 + (((lane >> 3) & 1) << 3);
                uint32_t ka = smb + base + (uint32_t)(br * AST + bc) * 2;
                uint32_t bh[4];
                ldsm4(bh[0], bh[1], bh[2], bh[3], ka);
                mma_f16(s[2 * g],     qf, bh);
                mma_f16(s[2 * g + 1], qf, bh + 2);
            }
        }

        float m0 = -1e30f, m1 = -1e30f;
#pragma unroll
        for (int nt = 0; nt < 8; nt++) {
            s[nt][0] *= sc; s[nt][1] *= sc; s[nt][2] *= sc; s[nt][3] *= sc;
            m0 = fmaxf(m0, fmaxf(s[nt][0], s[nt][1]));
            m1 = fmaxf(m1, fmaxf(s[nt][2], s[nt][3]));
        }
        m0 = fmaxf(m0, __shfl_xor_sync(0xffffffffu, m0, 1));
        m0 = fmaxf(m0, __shfl_xor_sync(0xffffffffu, m0, 2));
        m1 = fmaxf(m1, __shfl_xor_sync(0xffffffffu, m1, 1));
        m1 = fmaxf(m1, __shfl_xor_sync(0xffffffffu, m1, 2));
        float mn0 = fmaxf(m0s, m0), mn1 = fmaxf(m1s, m1);
        float a0 = exp2f(m0s - mn0), a1 = exp2f(m1s - mn1);
        m0s = mn0; m1s = mn1;
        float rs0 = 0.0f, rs1 = 0.0f;
#pragma unroll
        for (int nt = 0; nt < 8; nt++) {
            s[nt][0] = exp2f(s[nt][0] - mn0); rs0 += s[nt][0];
            s[nt][1] = exp2f(s[nt][1] - mn0); rs0 += s[nt][1];
            s[nt][2] = exp2f(s[nt][2] - mn1); rs1 += s[nt][2];
            s[nt][3] = exp2f(s[nt][3] - mn1); rs1 += s[nt][3];
        }
        rs0 += __shfl_xor_sync(0xffffffffu, rs0, 1);
        rs0 += __shfl_xor_sync(0xffffffffu, rs0, 2);
        rs1 += __shfl_xor_sync(0xffffffffu, rs1, 1);
        rs1 += __shfl_xor_sync(0xffffffffu, rs1, 2);
        l0s = l0s * a0 + rs0;
        l1s = l1s * a1 + rs1;
#pragma unroll
        for (int nt = 0; nt < 8; nt++) {
            oacc[nt][0] *= a0; oacc[nt][1] *= a0;
            oacc[nt][2] *= a1; oacc[nt][3] *= a1;
        }

        uint32_t pf[4][4];
#pragma unroll
        for (int j = 0; j < 4; j++) {
            pf[j][0] = pack2h(s[2 * j][0],     s[2 * j][1]);
            pf[j][1] = pack2h(s[2 * j][2],     s[2 * j][3]);
            pf[j][2] = pack2h(s[2 * j + 1][0], s[2 * j + 1][1]);
            pf[j][3] = pack2h(s[2 * j + 1][2], s[2 * j + 1][3]);
        }

#pragma unroll
        for (int j = 0; j < 4; j++) {
#pragma unroll
            for (int g = 0; g < 4; g++) {
                uint32_t va = smb + base + (uint32_t)(KV_PLANE +
                              (j * 16 + (lane & 15)) * AST + g * 16 +
                              ((lane >> 4) << 3)) * 2;
                uint32_t vh[4];
                ldsm4t(vh[0], vh[1], vh[2], vh[3], va);
                mma_f16(oacc[2 * g],     pf[j], vh);
                mma_f16(oacc[2 * g + 1], pf[j], vh + 2);
            }
        }
        __syncthreads();
    }

    float li0 = 1.0f / l0s, li1 = 1.0f / l1s;
#pragma unroll
    for (int half = 0; half < 2; half++) {
        int row = q0 + wid * 16 + half * 8 + (lane >> 2);
        float li = half ? li1 : li0;
        size_t baseo = (size_t)(b * NTOK + row) * DMODEL + h * 64 + (lane & 3) * 2;
#pragma unroll
        for (int nt = 0; nt < 8; nt++) {
            float v0 = oacc[nt][half * 2 + 0] * li;
            float v1 = oacc[nt][half * 2 + 1] * li;
            *(uint32_t*)(oh + baseo + nt * 8) = pack2h(v0, v1);
        }
    }
}

// ---------------- host orchestration ----------------------------------------
extern "C" void kernel_launch(void* const* d_in, const int* in_sizes, int n_in,
                              void* d_out, int out_size) {
    const float* x         = (const float*)d_in[0];
    const float* attn_ln_w = (const float*)d_in[1];
    const float* attn_ln_b = (const float*)d_in[2];
    const float* w_qkv     = (const float*)d_in[3];
    const float* w_out     = (const float*)d_in[4];
    const float* b_out     = (const float*)d_in[5];
    const float* ffn_ln_w  = (const float*)d_in[6];
    const float* ffn_ln_b  = (const float*)d_in[7];
    const float* w1        = (const float*)d_in[8];
    const float* b1        = (const float*)d_in[9];
    const float* w2        = (const float*)d_in[10];
    const float* b2        = (const float*)d_in[11];
    const float* ln_w      = (const float*)d_in[12];
    const float* ln_b      = (const float*)d_in[13];
    float* out = (float*)d_out;

    float* t;
    __half *qkv, *hh, *oh, *f1;
    __half *wqkv, *wout, *w1h, *w2h;
    cudaGetSymbolAddress((void**)&t,    g_t);
    cudaGetSymbolAddress((void**)&qkv,  g_qkv);
    cudaGetSymbolAddress((void**)&hh,   g_hh);
    cudaGetSymbolAddress((void**)&oh,   g_oh);
    cudaGetSymbolAddress((void**)&f1,   g_f1);
    cudaGetSymbolAddress((void**)&wqkv, g_wqkv);
    cudaGetSymbolAddress((void**)&wout, g_wout);
    cudaGetSymbolAddress((void**)&w1h,  g_w1);
    cudaGetSymbolAddress((void**)&w2h,  g_w2);

    cudaFuncSetAttribute(attn_tc, cudaFuncAttributeMaxDynamicSharedMemorySize, ATT_SMEM);
    cudaFuncSetAttribute(gemm_tc<1>, cudaFuncAttributeMaxDynamicSharedMemorySize, GEMM_SMEM);
    cudaFuncSetAttribute(gemm_tc<2>, cudaFuncAttributeMaxDynamicSharedMemorySize, GEMM_SMEM);
    cudaFuncSetAttribute(gemm_tc<3>, cudaFuncAttributeMaxDynamicSharedMemorySize, GEMM_SMEM);
    cudaFuncSetAttribute(ln_unembed_kernel, cudaFuncAttributeMaxDynamicSharedMemorySize,
                         32 * FLN_ST * 4);

    {
        const int n0 = DEPTH * 3 * DMODEL * DMODEL;
        const int n1 = DEPTH * DMODEL * DMODEL;
        const int n2 = 2 * DMODEL * DMODEL;
        const int n3 = 2 * DMODEL * DMODEL;
        const int ntot = n0 + n1 + n2 + n3;
        split_allh<<<(ntot + 255) / 256, 256>>>(
            w_qkv, wqkv, n0, w_out, wout, n1, w1, w1h, n2, w2, w2h, n3);
    }

    dim3 tb(32, 8);
    embed_kernel<<<dim3(32, 16, 8), tb>>>(x, t);

    for (int l = 0; l < DEPTH; l++) {
        ln_kernel<<<1024, 256>>>(t, attn_ln_w + l * DMODEL, attn_ln_b + l * DMODEL, hh);
        gemm_tc<3><<<dim3(6, 64), 256, GEMM_SMEM>>>(
            hh, wqkv + (size_t)l * 3 * DMODEL * DMODEL,
            nullptr, nullptr, nullptr, qkv, 3 * DMODEL, DMODEL);
        attn_tc<<<dim3(8, 64), 256, ATT_SMEM>>>(qkv, oh);
        gemm_tc<1><<<dim3(2, 64), 256, GEMM_SMEM>>>(
            oh, wout + (size_t)l * DMODEL * DMODEL,
            b_out + l * DMODEL, t, t, nullptr, DMODEL, DMODEL);
        ln_kernel<<<1024, 256>>>(t, ffn_ln_w, ffn_ln_b, hh);
        gemm_tc<2><<<dim3(4, 64), 256, GEMM_SMEM>>>(
            hh, w1h, b1, nullptr, nullptr, f1, 2 * DMODEL, DMODEL);
        gemm_tc<1><<<dim3(2, 64), 256, GEMM_SMEM>>>(
            f1, w2h, b2, t, t, nullptr, DMODEL, 2 * DMODEL);
    }

    ln_unembed_kernel<<<dim3(32, 8), 256, 32 * FLN_ST * 4>>>(t, ln_w, ln_b, out);
}

// round 16
// speedup vs baseline: 1.0373x; 1.0373x over previous
#include <cuda_runtime.h>
#include <cuda_fp16.h>
#include <math.h>
#include <stdint.h>

#define NTOK 1024
#define DMODEL 512
#define BATCH 8
#define DEPTH 4
#define ROWS (BATCH*NTOK)   // 8192

// ---------------- scratch (static device globals; no runtime allocation) ----
__device__ float g_t  [ROWS*DMODEL];
__device__ __half g_qkv[ROWS*3*DMODEL];
__device__ __half g_hh [ROWS*DMODEL];
__device__ __half g_oh [ROWS*DMODEL];
__device__ __half g_f1 [ROWS*2*DMODEL];
__device__ __half g_wqkv[DEPTH*3*DMODEL*DMODEL];
__device__ __half g_wout[DEPTH*DMODEL*DMODEL];
__device__ __half g_w1[2*DMODEL*DMODEL];
__device__ __half g_w2[2*DMODEL*DMODEL];

// ---------------- helpers ----------------------------------------------------
__device__ __forceinline__ uint32_t pack2h(float a, float b) {
    __half2 hp = __halves2half2(__float2half_rn(a), __float2half_rn(b));
    return *(uint32_t*)&hp;
}
__device__ __forceinline__ void ldsm4(uint32_t& r0, uint32_t& r1, uint32_t& r2, uint32_t& r3,
                                      uint32_t addr) {
    asm volatile("ldmatrix.sync.aligned.m8n8.x4.shared.b16 {%0,%1,%2,%3},[%4];"
                 : "=r"(r0), "=r"(r1), "=r"(r2), "=r"(r3) : "r"(addr));
}
__device__ __forceinline__ void ldsm4t(uint32_t& r0, uint32_t& r1, uint32_t& r2, uint32_t& r3,
                                       uint32_t addr) {
    asm volatile("ldmatrix.sync.aligned.m8n8.x4.trans.shared.b16 {%0,%1,%2,%3},[%4];"
                 : "=r"(r0), "=r"(r1), "=r"(r2), "=r"(r3) : "r"(addr));
}
__device__ __forceinline__ void mma_f16(float* c, const uint32_t* a, const uint32_t* b) {
    asm volatile(
        "mma.sync.aligned.m16n8k16.row.col.f32.f16.f16.f32 "
        "{%0,%1,%2,%3},{%4,%5,%6,%7},{%8,%9},{%0,%1,%2,%3};"
        : "+f"(c[0]), "+f"(c[1]), "+f"(c[2]), "+f"(c[3])
        : "r"(a[0]), "r"(a[1]), "r"(a[2]), "r"(a[3]), "r"(b[0]), "r"(b[1]));
}
__device__ __forceinline__ void cpasync16(uint32_t saddr, const void* g) {
    asm volatile("cp.async.cg.shared.global [%0],[%1],16;" :: "r"(saddr), "l"(g));
}
__device__ __forceinline__ float gelu_exact(float v) {
    return 0.5f * v * (1.0f + erff(v * 0.7071067811865476f));
}

// ---------------- fp16 convert of ALL weight tensors (one launch) -----------
__global__ void split_allh(const float* __restrict__ w0, __half* __restrict__ h0, int n0,
                           const float* __restrict__ w1, __half* __restrict__ h1, int n1,
                           const float* __restrict__ w2, __half* __restrict__ h2, int n2,
                           const float* __restrict__ w3, __half* __restrict__ h3, int n3) {
    int i = blockIdx.x * 256 + threadIdx.x;
    const float* w; __half* h;
    if (i < n0) { w = w0 + i; h = h0 + i; }
    else if (i < n0 + n1) { i -= n0; w = w1 + i; h = h1 + i; }
    else if (i < n0 + n1 + n2) { i -= n0 + n1; w = w2 + i; h = h2 + i; }
    else if (i < n0 + n1 + n2 + n3) { i -= n0 + n1 + n2; w = w3 + i; h = h3 + i; }
    else return;
    *h = __float2half_rn(*w);
}

// ---------------- embed: transpose [b,c,n] -> [b,n,c] + sinusoid PE ---------
__global__ void embed_kernel(const float* __restrict__ x, float* __restrict__ t) {
    __shared__ float tile[32][33];
    int n0 = blockIdx.x * 32, c0 = blockIdx.y * 32, b = blockIdx.z;
    int tx = threadIdx.x, ty = threadIdx.y;
#pragma unroll
    for (int i = 0; i < 4; i++) {
        int c = c0 + ty + i * 8;
        tile[ty + i * 8][tx] = x[((size_t)b * DMODEL + c) * NTOK + n0 + tx];
    }
    __syncthreads();
#pragma unroll
    for (int i = 0; i < 4; i++) {
        int n = n0 + ty + i * 8;
        int c = c0 + tx;
        float e = (float)(c & ~1) * (1.0f / DMODEL);
        float ang = (float)n * expf(-9.210340371976184f * e);
        float pe = (c & 1) ? cosf(ang) : sinf(ang);
        t[((size_t)b * NTOK + n) * DMODEL + c] = tile[tx][ty + i * 8] + pe;
    }
}

// ---------------- fused final LN + unembed transpose ------------------------
#define FLN_ST 513
__global__ void __launch_bounds__(256) ln_unembed_kernel(
    const float* __restrict__ t, const float* __restrict__ lw,
    const float* __restrict__ lb, float* __restrict__ out) {
    extern __shared__ float fsm[];
    const int tid = threadIdx.x, lane = tid & 31, w = tid >> 5;
    const int n0 = blockIdx.x * 32, b = blockIdx.y;

    const float4* wr = (const float4*)lw;
    const float4* br = (const float4*)lb;
#pragma unroll
    for (int rr = 0; rr < 4; rr++) {
        int rloc = w * 4 + rr;
        const float4* xr = (const float4*)(t + (size_t)(b * NTOK + n0 + rloc) * DMODEL);
        float4 v[4];
        float s = 0.0f;
#pragma unroll
        for (int u = 0; u < 4; u++) {
            v[u] = xr[u * 32 + lane];
            s += v[u].x + v[u].y + v[u].z + v[u].w;
        }
#pragma unroll
        for (int o = 16; o > 0; o >>= 1) s += __shfl_xor_sync(0xffffffffu, s, o);
        float mu = s * (1.0f / DMODEL);
        float q = 0.0f;
#pragma unroll
        for (int u = 0; u < 4; u++) {
            v[u].x -= mu; v[u].y -= mu; v[u].z -= mu; v[u].w -= mu;
            q += v[u].x * v[u].x + v[u].y * v[u].y + v[u].z * v[u].z + v[u].w * v[u].w;
        }
#pragma unroll
        for (int o = 16; o > 0; o >>= 1) q += __shfl_xor_sync(0xffffffffu, q, o);
        float rstd = rsqrtf(q * (1.0f / DMODEL) + 1e-5f);
        float* dst = fsm + rloc * FLN_ST;
#pragma unroll
        for (int u = 0; u < 4; u++) {
            float4 W = wr[u * 32 + lane], B = br[u * 32 + lane];
            int c = (u * 32 + lane) * 4;
            dst[c + 0] = v[u].x * rstd * W.x + B.x;
            dst[c + 1] = v[u].y * rstd * W.y + B.y;
            dst[c + 2] = v[u].z * rstd * W.z + B.z;
            dst[c + 3] = v[u].w * rstd * W.w + B.w;
        }
    }
    __syncthreads();

    const int nl = lane;
#pragma unroll 8
    for (int cb = 0; cb < DMODEL; cb += 8) {
        int c = cb + w;
        out[((size_t)b * DMODEL + c) * NTOK + n0 + nl] = fsm[nl * FLN_ST + c];
    }
}

// ---------------- layernorm -> fp16 plane (per-layer) -----------------------
__global__ void ln_kernel(const float* __restrict__ x, const float* __restrict__ w,
                          const float* __restrict__ bias, __half* __restrict__ yh) {
    int gw = (blockIdx.x * blockDim.x + threadIdx.x) >> 5;
    int lane = threadIdx.x & 31;
    if (gw >= ROWS) return;
    const float4* xr = (const float4*)(x + (size_t)gw * DMODEL);
    float4 v[4];
    float s = 0.0f;
#pragma unroll
    for (int u = 0; u < 4; u++) {
        v[u] = xr[u * 32 + lane];
        s += v[u].x + v[u].y + v[u].z + v[u].w;
    }
#pragma unroll
    for (int o = 16; o > 0; o >>= 1) s += __shfl_xor_sync(0xffffffffu, s, o);
    float mu = s * (1.0f / DMODEL);
    float q = 0.0f;
#pragma unroll
    for (int u = 0; u < 4; u++) {
        v[u].x -= mu; v[u].y -= mu; v[u].z -= mu; v[u].w -= mu;
        q += v[u].x * v[u].x + v[u].y * v[u].y + v[u].z * v[u].z + v[u].w * v[u].w;
    }
#pragma unroll
    for (int o = 16; o > 0; o >>= 1) q += __shfl_xor_sync(0xffffffffu, q, o);
    float rstd = rsqrtf(q * (1.0f / DMODEL) + 1e-5f);
    const float4* wr = (const float4*)w;
    const float4* br = (const float4*)bias;
#pragma unroll
    for (int u = 0; u < 4; u++) {
        float4 W = wr[u * 32 + lane], B = br[u * 32 + lane];
        float o0 = v[u].x * rstd * W.x + B.x;
        float o1 = v[u].y * rstd * W.y + B.y;
        float o2 = v[u].z * rstd * W.z + B.z;
        float o3 = v[u].w * rstd * W.w + B.w;
        size_t off = (size_t)gw * DMODEL + (u * 32 + lane) * 4;
        *(uint32_t*)(yh + off)     = pack2h(o0, o1);
        *(uint32_t*)(yh + off + 2) = pack2h(o2, o3);
    }
}

// ---------------- tensor-core GEMM (fp16): C = A * W^T ----------------------
#define BK 64
#define KST 72
#define PLANE (128*KST)        // 9216 halves
#define STAGE (2*PLANE)        // 18432 halves per stage
#define GEMM_SMEM (2*STAGE*2)  // 73728 bytes

// MODE 1: fp32 = acc+bias+resid. MODE 2: fp16 = gelu(acc+bias). MODE 3: fp16 = acc.
template <int MODE>
__global__ void __launch_bounds__(256, 2) gemm_tc(
    const __half* __restrict__ Ah, const __half* __restrict__ Bh,
    const float* __restrict__ bias, const float* __restrict__ resid,
    float* __restrict__ C, __half* __restrict__ Ch,
    int N, int K) {
    extern __shared__ __half smbuf[];
    const int tid = threadIdx.x;
    const int lane = tid & 31, w = tid >> 5;
    const int wr = w >> 2, wc = w & 3;
    const int m0 = blockIdx.y * 128, n0 = blockIdx.x * 128;
    const uint32_t smbase = (uint32_t)__cvta_generic_to_shared(smbuf);

    auto load_stage = [&](int it, int buf) {
        const int k0 = it * BK;
#pragma unroll
        for (int i = 0; i < 8; i++) {
            int c = tid + 256 * i;          // 0..2047
            int plane = c >> 10;            // 0:A 1:B
            int rem = c & 1023;
            int r = rem >> 3;               // row 0..127
            int cc = (rem & 7) * 8;
            const __half* src = plane ? (Bh + (size_t)(n0 + r) * K + k0 + cc)
                                      : (Ah + (size_t)(m0 + r) * K + k0 + cc);
            cpasync16(smbase + (uint32_t)(buf * STAGE + plane * PLANE + r * KST + cc) * 2,
                      src);
        }
    };

    float acc[4][4][4] = {};

    const int arow = wr * 64 + (lane & 15);
    const int acol = (lane >> 4) * 8;
    const int bn   = wc * 32 + ((lane >> 4) << 3) + (lane & 7);
    const int bk   = ((lane >> 3) & 1) << 3;

    const int niter = K / BK;
    load_stage(0, 0);
    asm volatile("cp.async.commit_group;");
    for (int it = 0; it < niter; ++it) {
        if (it + 1 < niter) {
            load_stage(it + 1, (it + 1) & 1);
            asm volatile("cp.async.commit_group;");
            asm volatile("cp.async.wait_group 1;");
        } else {
            asm volatile("cp.async.wait_group 0;");
        }
        __syncthreads();
        const uint32_t base = smbase + (uint32_t)(it & 1) * STAGE * 2;
#pragma unroll
        for (int kk = 0; kk < BK; kk += 16) {
            uint32_t af[4][4];
#pragma unroll
            for (int mt = 0; mt < 4; ++mt) {
                uint32_t ai = base + (uint32_t)((arow + mt * 16) * KST + kk + acol) * 2;
                ldsm4(af[mt][0], af[mt][1], af[mt][2], af[mt][3], ai);
            }
#pragma unroll
            for (int g = 0; g < 2; ++g) {
                uint32_t bf[4];
                uint32_t bi = base + PLANE * 2 +
                              (uint32_t)((bn + g * 16) * KST + kk + bk) * 2;
                ldsm4(bf[0], bf[1], bf[2], bf[3], bi);
#pragma unroll
                for (int half = 0; half < 2; ++half) {
                    int nt = 2 * g + half;
#pragma unroll
                    for (int mt = 0; mt < 4; ++mt)
                        mma_f16(acc[mt][nt], af[mt], bf + 2 * half);
                }
            }
        }
        __syncthreads();
    }

    const int erow = m0 + wr * 64 + (lane >> 2);
    const int ecol = n0 + wc * 32 + (lane & 3) * 2;
#pragma unroll
    for (int mt = 0; mt < 4; ++mt)
#pragma unroll
        for (int nt = 0; nt < 4; ++nt) {
            int c = ecol + nt * 8;
#pragma unroll
            for (int half = 0; half < 2; ++half) {
                int rr = erow + mt * 16 + half * 8;
                float v0 = acc[mt][nt][half * 2 + 0];
                float v1 = acc[mt][nt][half * 2 + 1];
                size_t off = (size_t)rr * N + c;
                if (MODE == 1) {
                    float2 rv = *(const float2*)(resid + off);
                    v0 += bias[c] + rv.x;
                    v1 += bias[c + 1] + rv.y;
                    *(float2*)(C + off) = make_float2(v0, v1);
                } else if (MODE == 2) {
                    v0 = gelu_exact(v0 + bias[c]);
                    v1 = gelu_exact(v1 + bias[c + 1]);
                    *(uint32_t*)(Ch + off) = pack2h(v0, v1);
                } else {
                    *(uint32_t*)(Ch + off) = pack2h(v0, v1);
                }
            }
        }
}

// ---------------- tensor-core flash attention (fp16, cp.async) --------------
#define AST 72
#define Q_ELE (128*AST)
#define KV_PLANE (64*AST)
#define STG_ELE (2*KV_PLANE)
#define ATT_SMEM ((Q_ELE + 2*STG_ELE)*2)   // 55296 bytes

__global__ void __launch_bounds__(256, 2) attn_tc(
    const __half* __restrict__ qkv, __half* __restrict__ oh) {
    extern __shared__ __half sb[];
    const uint32_t smb = (uint32_t)__cvta_generic_to_shared(sb);
    const int tid = threadIdx.x, lane = tid & 31, wid = tid >> 5;
    const int q0 = blockIdx.x * 128;
    const int b = blockIdx.y >> 3, h = blockIdx.y & 7;

    const __half* hbase = qkv + (size_t)(b * NTOK) * 1536 + h * 64;

#pragma unroll
    for (int i = 0; i < 4; i++) {
        int c = tid + 256 * i;
        int row = c >> 3, col = (c & 7) * 8;
        cpasync16(smb + (uint32_t)(row * AST + col) * 2,
                  hbase + (size_t)(q0 + row) * 1536 + col);
    }

    auto load_kv = [&](int kt, int buf) {
#pragma unroll
        for (int i = 0; i < 4; i++) {
            int c = tid + 256 * i;
            int plane = c >> 9, rem = c & 511;
            int row = rem >> 3, col = (rem & 7) * 8;
            const __half* src = hbase + (plane ? 1024 : 512) +
                                (size_t)(kt * 64 + row) * 1536 + col;
            uint32_t dst = (uint32_t)(Q_ELE + buf * STG_ELE + plane * KV_PLANE +
                                      row * AST + col) * 2;
            cpasync16(smb + dst, src);
        }
    };

    float oacc[8][4] = {};
    float m0s = -1e30f, m1s = -1e30f, l0s = 0.0f, l1s = 0.0f;
    const float sc = 0.18033688011112042f;

    load_kv(0, 0);
    asm volatile("cp.async.commit_group;");

    for (int kt = 0; kt < 16; kt++) {
        if (kt + 1 < 16) {
            load_kv(kt + 1, (kt + 1) & 1);
            asm volatile("cp.async.commit_group;");
            asm volatile("cp.async.wait_group 1;");
        } else {
            asm volatile("cp.async.wait_group 0;");
        }
        __syncthreads();
        const uint32_t base = (uint32_t)(Q_ELE + (kt & 1) * STG_ELE) * 2;

        float s[8][4] = {};
#pragma unroll
        for (int k8 = 0; k8 < 4; k8++) {
            uint32_t qf[4];
            uint32_t qa = smb + (uint32_t)((wid * 16 + (lane & 15)) * AST + k8 * 16 +
                                           ((lane >> 4) << 3)) * 2;
            ldsm4(qf[0], qf[1], qf[2], qf[3], qa);
#pragma unroll
            for (int g = 0; g < 4; g++) {
                int br = g * 16 + ((lane >> 4) << 3) + (lane & 7);
                int bc = k8 * 16 + (((lane >> 3) & 1) << 3);
                uint32_t ka = smb + base + (uint32_t)(br * AST + bc) * 2;
                uint32_t bh[4];
                ldsm4(bh[0], bh[1], bh[2], bh[3], ka);
                mma_f16(s[2 * g],     qf, bh);
                mma_f16(s[2 * g + 1], qf, bh + 2);
            }
        }

        float m0 = -1e30f, m1 = -1e30f;
#pragma unroll
        for (int nt = 0; nt < 8; nt++) {
            s[nt][0] *= sc; s[nt][1] *= sc; s[nt][2] *= sc; s[nt][3] *= sc;
            m0 = fmaxf(m0, fmaxf(s[nt][0], s[nt][1]));
            m1 = fmaxf(m1, fmaxf(s[nt][2], s[nt][3]));
        }
        m0 = fmaxf(m0, __shfl_xor_sync(0xffffffffu, m0, 1));
        m0 = fmaxf(m0, __shfl_xor_sync(0xffffffffu, m0, 2));
        m1 = fmaxf(m1, __shfl_xor_sync(0xffffffffu, m1, 1));
        m1 = fmaxf(m1, __shfl_xor_sync(0xffffffffu, m1, 2));
        float mn0 = fmaxf(m0s, m0), mn1 = fmaxf(m1s, m1);
        float a0 = exp2f(m0s - mn0), a1 = exp2f(m1s - mn1);
        m0s = mn0; m1s = mn1;
        float rs0 = 0.0f, rs1 = 0.0f;
#pragma unroll
        for (int nt = 0; nt < 8; nt++) {
            s[nt][0] = exp2f(s[nt][0] - mn0); rs0 += s[nt][0];
            s[nt][1] = exp2f(s[nt][1] - mn0); rs0 += s[nt][1];
            s[nt][2] = exp2f(s[nt][2] - mn1); rs1 += s[nt][2];
            s[nt][3] = exp2f(s[nt][3] - mn1); rs1 += s[nt][3];
        }
        rs0 += __shfl_xor_sync(0xffffffffu, rs0, 1);
        rs0 += __shfl_xor_sync(0xffffffffu, rs0, 2);
        rs1 += __shfl_xor_sync(0xffffffffu, rs1, 1);
        rs1 += __shfl_xor_sync(0xffffffffu, rs1, 2);
        l0s = l0s * a0 + rs0;
        l1s = l1s * a1 + rs1;
#pragma unroll
        for (int nt = 0; nt < 8; nt++) {
            oacc[nt][0] *= a0; oacc[nt][1] *= a0;
            oacc[nt][2] *= a1; oacc[nt][3] *= a1;
        }

        uint32_t pf[4][4];
#pragma unroll
        for (int j = 0; j < 4; j++) {
            pf[j][0] = pack2h(s[2 * j][0],     s[2 * j][1]);
            pf[j][1] = pack2h(s[2 * j][2],     s[2 * j][3]);
            pf[j][2] = pack2h(s[2 * j + 1][0], s[2 * j + 1][1]);
            pf[j][3] = pack2h(s[2 * j + 1][2], s[2 * j + 1][3]);
        }

#pragma unroll
        for (int j = 0; j < 4; j++) {
#pragma unroll
            for (int g = 0; g < 4; g++) {
                uint32_t va = smb + base + (uint32_t)(KV_PLANE +
                              (j * 16 + (lane & 15)) * AST + g * 16 +
                              ((lane >> 4) << 3)) * 2;
                uint32_t vh[4];
                ldsm4t(vh[0], vh[1], vh[2], vh[3], va);
                mma_f16(oacc[2 * g],     pf[j], vh);
                mma_f16(oacc[2 * g + 1], pf[j], vh + 2);
            }
        }
        __syncthreads();
    }

    float li0 = 1.0f / l0s, li1 = 1.0f / l1s;
#pragma unroll
    for (int half = 0; half < 2; half++) {
        int row = q0 + wid * 16 + half * 8 + (lane >> 2);
        float li = half ? li1 : li0;
        size_t baseo = (size_t)(b * NTOK + row) * DMODEL + h * 64 + (lane & 3) * 2;
#pragma unroll
        for (int nt = 0; nt < 8; nt++) {
            float v0 = oacc[nt][half * 2 + 0] * li;
            float v1 = oacc[nt][half * 2 + 1] * li;
            *(uint32_t*)(oh + baseo + nt * 8) = pack2h(v0, v1);
        }
    }
}

// ---------------- host orchestration ----------------------------------------
extern "C" void kernel_launch(void* const* d_in, const int* in_sizes, int n_in,
                              void* d_out, int out_size) {
    const float* x         = (const float*)d_in[0];
    const float* attn_ln_w = (const float*)d_in[1];
    const float* attn_ln_b = (const float*)d_in[2];
    const float* w_qkv     = (const float*)d_in[3];
    const float* w_out     = (const float*)d_in[4];
    const float* b_out     = (const float*)d_in[5];
    const float* ffn_ln_w  = (const float*)d_in[6];
    const float* ffn_ln_b  = (const float*)d_in[7];
    const float* w1        = (const float*)d_in[8];
    const float* b1        = (const float*)d_in[9];
    const float* w2        = (const float*)d_in[10];
    const float* b2        = (const float*)d_in[11];
    const float* ln_w      = (const float*)d_in[12];
    const float* ln_b      = (const float*)d_in[13];
    float* out = (float*)d_out;

    float* t;
    __half *qkv, *hh, *oh, *f1;
    __half *wqkv, *wout, *w1h, *w2h;
    cudaGetSymbolAddress((void**)&t,    g_t);
    cudaGetSymbolAddress((void**)&qkv,  g_qkv);
    cudaGetSymbolAddress((void**)&hh,   g_hh);
    cudaGetSymbolAddress((void**)&oh,   g_oh);
    cudaGetSymbolAddress((void**)&f1,   g_f1);
    cudaGetSymbolAddress((void**)&wqkv, g_wqkv);
    cudaGetSymbolAddress((void**)&wout, g_wout);
    cudaGetSymbolAddress((void**)&w1h,  g_w1);
    cudaGetSymbolAddress((void**)&w2h,  g_w2);

    cudaFuncSetAttribute(attn_tc, cudaFuncAttributeMaxDynamicSharedMemorySize, ATT_SMEM);
    cudaFuncSetAttribute(gemm_tc<1>, cudaFuncAttributeMaxDynamicSharedMemorySize, GEMM_SMEM);
    cudaFuncSetAttribute(gemm_tc<2>, cudaFuncAttributeMaxDynamicSharedMemorySize, GEMM_SMEM);
    cudaFuncSetAttribute(gemm_tc<3>, cudaFuncAttributeMaxDynamicSharedMemorySize, GEMM_SMEM);
    cudaFuncSetAttribute(ln_unembed_kernel, cudaFuncAttributeMaxDynamicSharedMemorySize,
                         32 * FLN_ST * 4);

    {
        const int n0 = DEPTH * 3 * DMODEL * DMODEL;
        const int n1 = DEPTH * DMODEL * DMODEL;
        const int n2 = 2 * DMODEL * DMODEL;
        const int n3 = 2 * DMODEL * DMODEL;
        const int ntot = n0 + n1 + n2 + n3;
        split_allh<<<(ntot + 255) / 256, 256>>>(
            w_qkv, wqkv, n0, w_out, wout, n1, w1, w1h, n2, w2, w2h, n3);
    }

    dim3 tb(32, 8);
    embed_kernel<<<dim3(32, 16, 8), tb>>>(x, t);

    for (int l = 0; l < DEPTH; l++) {
        ln_kernel<<<1024, 256>>>(t, attn_ln_w + l * DMODEL, attn_ln_b + l * DMODEL, hh);
        gemm_tc<3><<<dim3(12, 64), 256, GEMM_SMEM>>>(
            hh, wqkv + (size_t)l * 3 * DMODEL * DMODEL,
            nullptr, nullptr, nullptr, qkv, 3 * DMODEL, DMODEL);
        attn_tc<<<dim3(8, 64), 256, ATT_SMEM>>>(qkv, oh);
        gemm_tc<1><<<dim3(4, 64), 256, GEMM_SMEM>>>(
            oh, wout + (size_t)l * DMODEL * DMODEL,
            b_out + l * DMODEL, t, t, nullptr, DMODEL, DMODEL);
        ln_kernel<<<1024, 256>>>(t, ffn_ln_w, ffn_ln_b, hh);
        gemm_tc<2><<<dim3(8, 64), 256, GEMM_SMEM>>>(
            hh, w1h, b1, nullptr, nullptr, f1, 2 * DMODEL, DMODEL);
        gemm_tc<1><<<dim3(4, 64), 256, GEMM_SMEM>>>(
            f1, w2h, b2, t, t, nullptr, DMODEL, 2 * DMODEL);
    }

    ln_unembed_kernel<<<dim3(32, 8), 256, 32 * FLN_ST * 4>>>(t, ln_w, ln_b, out);
}

// round 17
// speedup vs baseline: 1.0938x; 1.0545x over previous
#include <cuda_runtime.h>
#include <cuda_fp16.h>
#include <math.h>
#include <stdint.h>

#define NTOK 1024
#define DMODEL 512
#define BATCH 8
#define DEPTH 4
#define ROWS (BATCH*NTOK)   // 8192

// ---------------- scratch (static device globals; no runtime allocation) ----
__device__ float g_t  [ROWS*DMODEL];
__device__ __half g_qkv[ROWS*3*DMODEL];
__device__ __half g_hh [ROWS*DMODEL];
__device__ __half g_oh [ROWS*DMODEL];
__device__ __half g_f1 [ROWS*2*DMODEL];
__device__ __half g_wqkv[DEPTH*3*DMODEL*DMODEL];
__device__ __half g_wout[DEPTH*DMODEL*DMODEL];
__device__ __half g_w1[2*DMODEL*DMODEL];
__device__ __half g_w2[2*DMODEL*DMODEL];

// ---------------- helpers ----------------------------------------------------
__device__ __forceinline__ uint32_t pack2h(float a, float b) {
    __half2 hp = __halves2half2(__float2half_rn(a), __float2half_rn(b));
    return *(uint32_t*)&hp;
}
__device__ __forceinline__ void ldsm4(uint32_t& r0, uint32_t& r1, uint32_t& r2, uint32_t& r3,
                                      uint32_t addr) {
    asm volatile("ldmatrix.sync.aligned.m8n8.x4.shared.b16 {%0,%1,%2,%3},[%4];"
                 : "=r"(r0), "=r"(r1), "=r"(r2), "=r"(r3) : "r"(addr));
}
__device__ __forceinline__ void ldsm4t(uint32_t& r0, uint32_t& r1, uint32_t& r2, uint32_t& r3,
                                       uint32_t addr) {
    asm volatile("ldmatrix.sync.aligned.m8n8.x4.trans.shared.b16 {%0,%1,%2,%3},[%4];"
                 : "=r"(r0), "=r"(r1), "=r"(r2), "=r"(r3) : "r"(addr));
}
__device__ __forceinline__ void mma_f16(float* c, const uint32_t* a, const uint32_t* b) {
    asm volatile(
        "mma.sync.aligned.m16n8k16.row.col.f32.f16.f16.f32 "
        "{%0,%1,%2,%3},{%4,%5,%6,%7},{%8,%9},{%0,%1,%2,%3};"
        : "+f"(c[0]), "+f"(c[1]), "+f"(c[2]), "+f"(c[3])
        : "r"(a[0]), "r"(a[1]), "r"(a[2]), "r"(a[3]), "r"(b[0]), "r"(b[1]));
}
__device__ __forceinline__ void cpasync16(uint32_t saddr, const void* g) {
    asm volatile("cp.async.cg.shared.global [%0],[%1],16;" :: "r"(saddr), "l"(g));
}
__device__ __forceinline__ float gelu_exact(float v) {
    return 0.5f * v * (1.0f + erff(v * 0.7071067811865476f));
}

// ---------------- fp16 convert of ALL weight tensors (one launch) -----------
__global__ void split_allh(const float* __restrict__ w0, __half* __restrict__ h0, int n0,
                           const float* __restrict__ w1, __half* __restrict__ h1, int n1,
                           const float* __restrict__ w2, __half* __restrict__ h2, int n2,
                           const float* __restrict__ w3, __half* __restrict__ h3, int n3) {
    int i = blockIdx.x * 256 + threadIdx.x;
    const float* w; __half* h;
    if (i < n0) { w = w0 + i; h = h0 + i; }
    else if (i < n0 + n1) { i -= n0; w = w1 + i; h = h1 + i; }
    else if (i < n0 + n1 + n2) { i -= n0 + n1; w = w2 + i; h = h2 + i; }
    else if (i < n0 + n1 + n2 + n3) { i -= n0 + n1 + n2; w = w3 + i; h = h3 + i; }
    else return;
    *h = __float2half_rn(*w);
}

// ---------------- embed: transpose [b,c,n] -> [b,n,c] + sinusoid PE ---------
__global__ void embed_kernel(const float* __restrict__ x, float* __restrict__ t) {
    __shared__ float tile[32][33];
    int n0 = blockIdx.x * 32, c0 = blockIdx.y * 32, b = blockIdx.z;
    int tx = threadIdx.x, ty = threadIdx.y;
#pragma unroll
    for (int i = 0; i < 4; i++) {
        int c = c0 + ty + i * 8;
        tile[ty + i * 8][tx] = x[((size_t)b * DMODEL + c) * NTOK + n0 + tx];
    }
    __syncthreads();
#pragma unroll
    for (int i = 0; i < 4; i++) {
        int n = n0 + ty + i * 8;
        int c = c0 + tx;
        float e = (float)(c & ~1) * (1.0f / DMODEL);
        float ang = (float)n * expf(-9.210340371976184f * e);
        float pe = (c & 1) ? cosf(ang) : sinf(ang);
        t[((size_t)b * NTOK + n) * DMODEL + c] = tile[tx][ty + i * 8] + pe;
    }
}

// ---------------- fused final LN + unembed transpose ------------------------
#define FLN_ST 513
__global__ void __launch_bounds__(256) ln_unembed_kernel(
    const float* __restrict__ t, const float* __restrict__ lw,
    const float* __restrict__ lb, float* __restrict__ out) {
    extern __shared__ float fsm[];
    const int tid = threadIdx.x, lane = tid & 31, w = tid >> 5;
    const int n0 = blockIdx.x * 32, b = blockIdx.y;

    const float4* wr = (const float4*)lw;
    const float4* br = (const float4*)lb;
#pragma unroll
    for (int rr = 0; rr < 4; rr++) {
        int rloc = w * 4 + rr;
        const float4* xr = (const float4*)(t + (size_t)(b * NTOK + n0 + rloc) * DMODEL);
        float4 v[4];
        float s = 0.0f;
#pragma unroll
        for (int u = 0; u < 4; u++) {
            v[u] = xr[u * 32 + lane];
            s += v[u].x + v[u].y + v[u].z + v[u].w;
        }
#pragma unroll
        for (int o = 16; o > 0; o >>= 1) s += __shfl_xor_sync(0xffffffffu, s, o);
        float mu = s * (1.0f / DMODEL);
        float q = 0.0f;
#pragma unroll
        for (int u = 0; u < 4; u++) {
            v[u].x -= mu; v[u].y -= mu; v[u].z -= mu; v[u].w -= mu;
            q += v[u].x * v[u].x + v[u].y * v[u].y + v[u].z * v[u].z + v[u].w * v[u].w;
        }
#pragma unroll
        for (int o = 16; o > 0; o >>= 1) q += __shfl_xor_sync(0xffffffffu, q, o);
        float rstd = rsqrtf(q * (1.0f / DMODEL) + 1e-5f);
        float* dst = fsm + rloc * FLN_ST;
#pragma unroll
        for (int u = 0; u < 4; u++) {
            float4 W = wr[u * 32 + lane], B = br[u * 32 + lane];
            int c = (u * 32 + lane) * 4;
            dst[c + 0] = v[u].x * rstd * W.x + B.x;
            dst[c + 1] = v[u].y * rstd * W.y + B.y;
            dst[c + 2] = v[u].z * rstd * W.z + B.z;
            dst[c + 3] = v[u].w * rstd * W.w + B.w;
        }
    }
    __syncthreads();

    const int nl = lane;
#pragma unroll 8
    for (int cb = 0; cb < DMODEL; cb += 8) {
        int c = cb + w;
        out[((size_t)b * DMODEL + c) * NTOK + n0 + nl] = fsm[nl * FLN_ST + c];
    }
}

// ---------------- layernorm -> fp16 plane (per-layer) -----------------------
__global__ void ln_kernel(const float* __restrict__ x, const float* __restrict__ w,
                          const float* __restrict__ bias, __half* __restrict__ yh) {
    int gw = (blockIdx.x * blockDim.x + threadIdx.x) >> 5;
    int lane = threadIdx.x & 31;
    if (gw >= ROWS) return;
    const float4* xr = (const float4*)(x + (size_t)gw * DMODEL);
    float4 v[4];
    float s = 0.0f;
#pragma unroll
    for (int u = 0; u < 4; u++) {
        v[u] = xr[u * 32 + lane];
        s += v[u].x + v[u].y + v[u].z + v[u].w;
    }
#pragma unroll
    for (int o = 16; o > 0; o >>= 1) s += __shfl_xor_sync(0xffffffffu, s, o);
    float mu = s * (1.0f / DMODEL);
    float q = 0.0f;
#pragma unroll
    for (int u = 0; u < 4; u++) {
        v[u].x -= mu; v[u].y -= mu; v[u].z -= mu; v[u].w -= mu;
        q += v[u].x * v[u].x + v[u].y * v[u].y + v[u].z * v[u].z + v[u].w * v[u].w;
    }
#pragma unroll
    for (int o = 16; o > 0; o >>= 1) q += __shfl_xor_sync(0xffffffffu, q, o);
    float rstd = rsqrtf(q * (1.0f / DMODEL) + 1e-5f);
    const float4* wr = (const float4*)w;
    const float4* br = (const float4*)bias;
#pragma unroll
    for (int u = 0; u < 4; u++) {
        float4 W = wr[u * 32 + lane], B = br[u * 32 + lane];
        float o0 = v[u].x * rstd * W.x + B.x;
        float o1 = v[u].y * rstd * W.y + B.y;
        float o2 = v[u].z * rstd * W.z + B.z;
        float o3 = v[u].w * rstd * W.w + B.w;
        size_t off = (size_t)gw * DMODEL + (u * 32 + lane) * 4;
        *(uint32_t*)(yh + off)     = pack2h(o0, o1);
        *(uint32_t*)(yh + off + 2) = pack2h(o2, o3);
    }
}

// ---------------- tensor-core GEMM (fp16): C = A * W^T ----------------------
#define BK 64
#define KST 72
#define PLANE (128*KST)        // 9216 halves
#define STAGE (2*PLANE)        // 18432 halves per stage
#define GEMM_SMEM (2*STAGE*2)  // 73728 bytes

// MODE 1: fp32 = acc+bias+resid. MODE 2: fp16 = gelu(acc+bias). MODE 3: fp16 = acc.
// N, K compile-time: unrolled k-loop, strength-reduced addressing.
template <int MODE, int N, int K>
__global__ void __launch_bounds__(256, 2) gemm_tc(
    const __half* __restrict__ Ah, const __half* __restrict__ Bh,
    const float* __restrict__ bias, const float* __restrict__ resid,
    float* __restrict__ C, __half* __restrict__ Ch) {
    extern __shared__ __half smbuf[];
    const int tid = threadIdx.x;
    const int lane = tid & 31, w = tid >> 5;
    const int wr = w >> 2, wc = w & 3;
    const int m0 = blockIdx.y * 128, n0 = blockIdx.x * 128;
    const uint32_t smbase = (uint32_t)__cvta_generic_to_shared(smbuf);

    auto load_stage = [&](int it, int buf) {
        const int k0 = it * BK;
#pragma unroll
        for (int i = 0; i < 8; i++) {
            int c = tid + 256 * i;          // 0..2047
            int plane = c >> 10;            // 0:A 1:B
            int rem = c & 1023;
            int r = rem >> 3;               // row 0..127
            int cc = (rem & 7) * 8;
            const __half* src = plane ? (Bh + (size_t)(n0 + r) * K + k0 + cc)
                                      : (Ah + (size_t)(m0 + r) * K + k0 + cc);
            cpasync16(smbase + (uint32_t)(buf * STAGE + plane * PLANE + r * KST + cc) * 2,
                      src);
        }
    };

    float acc[4][4][4] = {};

    const int arow = wr * 64 + (lane & 15);
    const int acol = (lane >> 4) * 8;
    const int bn   = wc * 32 + ((lane >> 4) << 3) + (lane & 7);
    const int bk   = ((lane >> 3) & 1) << 3;

    constexpr int niter = K / BK;
    load_stage(0, 0);
    asm volatile("cp.async.commit_group;");
#pragma unroll
    for (int it = 0; it < niter; ++it) {
        if (it + 1 < niter) {
            load_stage(it + 1, (it + 1) & 1);
            asm volatile("cp.async.commit_group;");
            asm volatile("cp.async.wait_group 1;");
        } else {
            asm volatile("cp.async.wait_group 0;");
        }
        __syncthreads();
        const uint32_t base = smbase + (uint32_t)(it & 1) * STAGE * 2;
#pragma unroll
        for (int kk = 0; kk < BK; kk += 16) {
            uint32_t af[4][4];
#pragma unroll
            for (int mt = 0; mt < 4; ++mt) {
                uint32_t ai = base + (uint32_t)((arow + mt * 16) * KST + kk + acol) * 2;
                ldsm4(af[mt][0], af[mt][1], af[mt][2], af[mt][3], ai);
            }
#pragma unroll
            for (int g = 0; g < 2; ++g) {
                uint32_t bf[4];
                uint32_t bi = base + PLANE * 2 +
                              (uint32_t)((bn + g * 16) * KST + kk + bk) * 2;
                ldsm4(bf[0], bf[1], bf[2], bf[3], bi);
#pragma unroll
                for (int half = 0; half < 2; ++half) {
                    int nt = 2 * g + half;
#pragma unroll
                    for (int mt = 0; mt < 4; ++mt)
                        mma_f16(acc[mt][nt], af[mt], bf + 2 * half);
                }
            }
        }
        __syncthreads();
    }

    const int erow = m0 + wr * 64 + (lane >> 2);
    const int ecol = n0 + wc * 32 + (lane & 3) * 2;
#pragma unroll
    for (int mt = 0; mt < 4; ++mt)
#pragma unroll
        for (int nt = 0; nt < 4; ++nt) {
            int c = ecol + nt * 8;
#pragma unroll
            for (int half = 0; half < 2; ++half) {
                int rr = erow + mt * 16 + half * 8;
                float v0 = acc[mt][nt][half * 2 + 0];
                float v1 = acc[mt][nt][half * 2 + 1];
                size_t off = (size_t)rr * N + c;
                if (MODE == 1) {
                    float2 rv = *(const float2*)(resid + off);
                    v0 += bias[c] + rv.x;
                    v1 += bias[c + 1] + rv.y;
                    *(float2*)(C + off) = make_float2(v0, v1);
                } else if (MODE == 2) {
                    v0 = gelu_exact(v0 + bias[c]);
                    v1 = gelu_exact(v1 + bias[c + 1]);
                    *(uint32_t*)(Ch + off) = pack2h(v0, v1);
                } else {
                    *(uint32_t*)(Ch + off) = pack2h(v0, v1);
                }
            }
        }
}

// ---------------- tensor-core flash attention (fp16, cp.async) --------------
#define AST 72
#define Q_ELE (128*AST)
#define KV_PLANE (64*AST)
#define STG_ELE (2*KV_PLANE)
#define ATT_SMEM ((Q_ELE + 2*STG_ELE)*2)   // 55296 bytes

__global__ void __launch_bounds__(256, 2) attn_tc(
    const __half* __restrict__ qkv, __half* __restrict__ oh) {
    extern __shared__ __half sb[];
    const uint32_t smb = (uint32_t)__cvta_generic_to_shared(sb);
    const int tid = threadIdx.x, lane = tid & 31, wid = tid >> 5;
    const int q0 = blockIdx.x * 128;
    const int b = blockIdx.y >> 3, h = blockIdx.y & 7;

    const __half* hbase = qkv + (size_t)(b * NTOK) * 1536 + h * 64;

#pragma unroll
    for (int i = 0; i < 4; i++) {
        int c = tid + 256 * i;
        int row = c >> 3, col = (c & 7) * 8;
        cpasync16(smb + (uint32_t)(row * AST + col) * 2,
                  hbase + (size_t)(q0 + row) * 1536 + col);
    }

    auto load_kv = [&](int kt, int buf) {
#pragma unroll
        for (int i = 0; i < 4; i++) {
            int c = tid + 256 * i;
            int plane = c >> 9, rem = c & 511;
            int row = rem >> 3, col = (rem & 7) * 8;
            const __half* src = hbase + (plane ? 1024 : 512) +
                                (size_t)(kt * 64 + row) * 1536 + col;
            uint32_t dst = (uint32_t)(Q_ELE + buf * STG_ELE + plane * KV_PLANE +
                                      row * AST + col) * 2;
            cpasync16(smb + dst, src);
        }
    };

    float oacc[8][4] = {};
    float m0s = -1e30f, m1s = -1e30f, l0s = 0.0f, l1s = 0.0f;
    const float sc = 0.18033688011112042f;

    load_kv(0, 0);
    asm volatile("cp.async.commit_group;");

    for (int kt = 0; kt < 16; kt++) {
        if (kt + 1 < 16) {
            load_kv(kt + 1, (kt + 1) & 1);
            asm volatile("cp.async.commit_group;");
            asm volatile("cp.async.wait_group 1;");
        } else {
            asm volatile("cp.async.wait_group 0;");
        }
        __syncthreads();
        const uint32_t base = (uint32_t)(Q_ELE + (kt & 1) * STG_ELE) * 2;

        float s[8][4] = {};
#pragma unroll
        for (int k8 = 0; k8 < 4; k8++) {
            uint32_t qf[4];
            uint32_t qa = smb + (uint32_t)((wid * 16 + (lane & 15)) * AST + k8 * 16 +
                                           ((lane >> 4) << 3)) * 2;
            ldsm4(qf[0], qf[1], qf[2], qf[3], qa);
#pragma unroll
            for (int g = 0; g < 4; g++) {
                int br = g * 16 + ((lane >> 4) << 3) + (lane & 7);
                int bc = k8 * 16 + (((lane >> 3) & 1) << 3);
                uint32_t ka = smb + base + (uint32_t)(br * AST + bc) * 2;
                uint32_t bh[4];
                ldsm4(bh[0], bh[1], bh[2], bh[3], ka);
                mma_f16(s[2 * g],     qf, bh);
                mma_f16(s[2 * g + 1], qf, bh + 2);
            }
        }

        float m0 = -1e30f, m1 = -1e30f;
#pragma unroll
        for (int nt = 0; nt < 8; nt++) {
            s[nt][0] *= sc; s[nt][1] *= sc; s[nt][2] *= sc; s[nt][3] *= sc;
            m0 = fmaxf(m0, fmaxf(s[nt][0], s[nt][1]));
            m1 = fmaxf(m1, fmaxf(s[nt][2], s[nt][3]));
        }
        m0 = fmaxf(m0, __shfl_xor_sync(0xffffffffu, m0, 1));
        m0 = fmaxf(m0, __shfl_xor_sync(0xffffffffu, m0, 2));
        m1 = fmaxf(m1, __shfl_xor_sync(0xffffffffu, m1, 1));
        m1 = fmaxf(m1, __shfl_xor_sync(0xffffffffu, m1, 2));
        float mn0 = fmaxf(m0s, m0), mn1 = fmaxf(m1s, m1);
        float a0 = exp2f(m0s - mn0), a1 = exp2f(m1s - mn1);
        m0s = mn0; m1s = mn1;
        float rs0 = 0.0f, rs1 = 0.0f;
#pragma unroll
        for (int nt = 0; nt < 8; nt++) {
            s[nt][0] = exp2f(s[nt][0] - mn0); rs0 += s[nt][0];
            s[nt][1] = exp2f(s[nt][1] - mn0); rs0 += s[nt][1];
            s[nt][2] = exp2f(s[nt][2] - mn1); rs1 += s[nt][2];
            s[nt][3] = exp2f(s[nt][3] - mn1); rs1 += s[nt][3];
        }
        rs0 += __shfl_xor_sync(0xffffffffu, rs0, 1);
        rs0 += __shfl_xor_sync(0xffffffffu, rs0, 2);
        rs1 += __shfl_xor_sync(0xffffffffu, rs1, 1);
        rs1 += __shfl_xor_sync(0xffffffffu, rs1, 2);
        l0s = l0s * a0 + rs0;
        l1s = l1s * a1 + rs1;
#pragma unroll
        for (int nt = 0; nt < 8; nt++) {
            oacc[nt][0] *= a0; oacc[nt][1] *= a0;
            oacc[nt][2] *= a1; oacc[nt][3] *= a1;
        }

        uint32_t pf[4][4];
#pragma unroll
        for (int j = 0; j < 4; j++) {
            pf[j][0] = pack2h(s[2 * j][0],     s[2 * j][1]);
            pf[j][1] = pack2h(s[2 * j][2],     s[2 * j][3]);
            pf[j][2] = pack2h(s[2 * j + 1][0], s[2 * j + 1][1]);
            pf[j][3] = pack2h(s[2 * j + 1][2], s[2 * j + 1][3]);
        }

#pragma unroll
        for (int j = 0; j < 4; j++) {
#pragma unroll
            for (int g = 0; g < 4; g++) {
                uint32_t va = smb + base + (uint32_t)(KV_PLANE +
                              (j * 16 + (lane & 15)) * AST + g * 16 +
                              ((lane >> 4) << 3)) * 2;
                uint32_t vh[4];
                ldsm4t(vh[0], vh[1], vh[2], vh[3], va);
                mma_f16(oacc[2 * g],     pf[j], vh);
                mma_f16(oacc[2 * g + 1], pf[j], vh + 2);
            }
        }
        __syncthreads();
    }

    float li0 = 1.0f / l0s, li1 = 1.0f / l1s;
#pragma unroll
    for (int half = 0; half < 2; half++) {
        int row = q0 + wid * 16 + half * 8 + (lane >> 2);
        float li = half ? li1 : li0;
        size_t baseo = (size_t)(b * NTOK + row) * DMODEL + h * 64 + (lane & 3) * 2;
#pragma unroll
        for (int nt = 0; nt < 8; nt++) {
            float v0 = oacc[nt][half * 2 + 0] * li;
            float v1 = oacc[nt][half * 2 + 1] * li;
            *(uint32_t*)(oh + baseo + nt * 8) = pack2h(v0, v1);
        }
    }
}

// ---------------- host orchestration ----------------------------------------
extern "C" void kernel_launch(void* const* d_in, const int* in_sizes, int n_in,
                              void* d_out, int out_size) {
    const float* x         = (const float*)d_in[0];
    const float* attn_ln_w = (const float*)d_in[1];
    const float* attn_ln_b = (const float*)d_in[2];
    const float* w_qkv     = (const float*)d_in[3];
    const float* w_out     = (const float*)d_in[4];
    const float* b_out     = (const float*)d_in[5];
    const float* ffn_ln_w  = (const float*)d_in[6];
    const float* ffn_ln_b  = (const float*)d_in[7];
    const float* w1        = (const float*)d_in[8];
    const float* b1        = (const float*)d_in[9];
    const float* w2        = (const float*)d_in[10];
    const float* b2        = (const float*)d_in[11];
    const float* ln_w      = (const float*)d_in[12];
    const float* ln_b      = (const float*)d_in[13];
    float* out = (float*)d_out;

    float* t;
    __half *qkv, *hh, *oh, *f1;
    __half *wqkv, *wout, *w1h, *w2h;
    cudaGetSymbolAddress((void**)&t,    g_t);
    cudaGetSymbolAddress((void**)&qkv,  g_qkv);
    cudaGetSymbolAddress((void**)&hh,   g_hh);
    cudaGetSymbolAddress((void**)&oh,   g_oh);
    cudaGetSymbolAddress((void**)&f1,   g_f1);
    cudaGetSymbolAddress((void**)&wqkv, g_wqkv);
    cudaGetSymbolAddress((void**)&wout, g_wout);
    cudaGetSymbolAddress((void**)&w1h,  g_w1);
    cudaGetSymbolAddress((void**)&w2h,  g_w2);

    cudaFuncSetAttribute(attn_tc, cudaFuncAttributeMaxDynamicSharedMemorySize, ATT_SMEM);
    cudaFuncSetAttribute((gemm_tc<3, 1536, 512>), cudaFuncAttributeMaxDynamicSharedMemorySize, GEMM_SMEM);
    cudaFuncSetAttribute((gemm_tc<1, 512, 512>),  cudaFuncAttributeMaxDynamicSharedMemorySize, GEMM_SMEM);
    cudaFuncSetAttribute((gemm_tc<2, 1024, 512>), cudaFuncAttributeMaxDynamicSharedMemorySize, GEMM_SMEM);
    cudaFuncSetAttribute((gemm_tc<1, 512, 1024>), cudaFuncAttributeMaxDynamicSharedMemorySize, GEMM_SMEM);
    cudaFuncSetAttribute(ln_unembed_kernel, cudaFuncAttributeMaxDynamicSharedMemorySize,
                         32 * FLN_ST * 4);

    {
        const int n0 = DEPTH * 3 * DMODEL * DMODEL;
        const int n1 = DEPTH * DMODEL * DMODEL;
        const int n2 = 2 * DMODEL * DMODEL;
        const int n3 = 2 * DMODEL * DMODEL;
        const int ntot = n0 + n1 + n2 + n3;
        split_allh<<<(ntot + 255) / 256, 256>>>(
            w_qkv, wqkv, n0, w_out, wout, n1, w1, w1h, n2, w2, w2h, n3);
    }

    dim3 tb(32, 8);
    embed_kernel<<<dim3(32, 16, 8), tb>>>(x, t);

    for (int l = 0; l < DEPTH; l++) {
        ln_kernel<<<1024, 256>>>(t, attn_ln_w + l * DMODEL, attn_ln_b + l * DMODEL, hh);
        gemm_tc<3, 1536, 512><<<dim3(12, 64), 256, GEMM_SMEM>>>(
            hh, wqkv + (size_t)l * 3 * DMODEL * DMODEL,
            nullptr, nullptr, nullptr, qkv);
        attn_tc<<<dim3(8, 64), 256, ATT_SMEM>>>(qkv, oh);
        gemm_tc<1, 512, 512><<<dim3(4, 64), 256, GEMM_SMEM>>>(
            oh, wout + (size_t)l * DMODEL * DMODEL,
            b_out + l * DMODEL, t, t, nullptr);
        ln_kernel<<<1024, 256>>>(t, ffn_ln_w, ffn_ln_b, hh);
        gemm_tc<2, 1024, 512><<<dim3(8, 64), 256, GEMM_SMEM>>>(
            hh, w1h, b1, nullptr, nullptr, f1);
        gemm_tc<1, 512, 1024><<<dim3(4, 64), 256, GEMM_SMEM>>>(
            f1, w2h, b2, t, t, nullptr);
    }

    ln_unembed_kernel<<<dim3(32, 8), 256, 32 * FLN_ST * 4>>>(t, ln_w, ln_b, out);
}